// round 16
// baseline (speedup 1.0000x reference)
#include <cuda_runtime.h>
#include <cuda_bf16.h>
#include <math_constants.h>

// Problem shape (fixed by dataset)
#define NN 100000
#define NE 1600000
#define INF_ 128
#define OUTF 64
#define SCAN_NB 391          // ceil(NN/256)

// ---------------- device scratch (static: no runtime allocation) -------------
// NOTE lifecycle: g_deg is zero at every kernel_launch entry — zero-initialized
// at load, and re-zeroed by k_aggregate at the end of every executed call
// (graph capture does not execute, so the invariant holds across replays).
__device__ float g_ft[(size_t)NN * OUTF];       // projected features  [N,64]
__device__ int   g_deg[NN];                     // in-degree histogram
__device__ int   g_offs[NN + 1];                // CSR offsets by dst
__device__ int   g_cursor[NN];                  // scatter cursors
__device__ int   g_csr_src[NE];                 // src node per CSR slot
__device__ unsigned long long g_state[SCAN_NB]; // lookback: (status<<32)|sum

__device__ __forceinline__ int clampidx(int v) {
    unsigned u = (unsigned)v;
    return (u < (unsigned)NN) ? v : 0;
}

// packed f32x2 helpers (Blackwell: FFMA2 only reachable from PTX)
__device__ __forceinline__ unsigned long long pack2(float lo, float hi) {
    unsigned long long r;
    asm("mov.b64 %0, {%1, %2};" : "=l"(r) : "f"(lo), "f"(hi));
    return r;
}
__device__ __forceinline__ void unpack2(unsigned long long v, float& lo, float& hi) {
    asm("mov.b64 {%0, %1}, %2;" : "=f"(lo), "=f"(hi) : "l"(v));
}
__device__ __forceinline__ void fma2(unsigned long long& d,
                                     unsigned long long a, unsigned long long b) {
    asm("fma.rn.f32x2 %0, %1, %2, %0;" : "+l"(d) : "l"(a), "l"(b));
}

// half-warp fold reduce of an (even, odd) edge pair -> both lanes get both sums
__device__ __forceinline__ void fold_pair(float pe, float po, bool hi16,
                                          float& ae, float& ao) {
    float u = hi16 ? po : pe;
    u += __shfl_xor_sync(0xffffffffu, hi16 ? pe : po, 16);
#pragma unroll
    for (int o = 8; o; o >>= 1) u += __shfl_xor_sync(0xffffffffu, u, o);
    float ot = __shfl_xor_sync(0xffffffffu, u, 16);
    ae = hi16 ? ot : u;
    ao = hi16 ? u : ot;
}

// ---------------- K1: in-degree histogram + scan-state reset -----------------
__global__ __launch_bounds__(256) void k_deg(const int* __restrict__ dst) {
    int t = blockIdx.x * blockDim.x + threadIdx.x;
    if (t < SCAN_NB) g_state[t] = 0ull;       // consumed by k_scan (next launch)
    if (t >= NE / 4) return;
    int4 d4 = ((const int4*)dst)[t];
    atomicAdd(&g_deg[clampidx(d4.x)], 1);
    atomicAdd(&g_deg[clampidx(d4.y)], 1);
    atomicAdd(&g_deg[clampidx(d4.z)], 1);
    atomicAdd(&g_deg[clampidx(d4.w)], 1);
}

// ---------------- K2: single-pass decoupled-lookback exclusive scan ----------
__global__ __launch_bounds__(256) void k_scan() {
    __shared__ int wsum[8];
    __shared__ int bprefix;
    int b = blockIdx.x;
    int tid = threadIdx.x;
    int lane = tid & 31;
    int wid = tid >> 5;
    int i = b * 256 + tid;

    int v = (i < NN) ? g_deg[i] : 0;
    int x = v;
#pragma unroll
    for (int o = 1; o < 32; o <<= 1) {
        int t = __shfl_up_sync(0xffffffffu, x, o);
        if (lane >= o) x += t;
    }
    if (lane == 31) wsum[wid] = x;
    __syncthreads();
    if (wid == 0) {
        int y = (lane < 8) ? wsum[lane] : 0;
#pragma unroll
        for (int o = 1; o < 8; o <<= 1) {
            int t = __shfl_up_sync(0xffffffffu, y, o);
            if (lane >= o) y += t;
        }
        if (lane < 8) wsum[lane] = y;
    }
    __syncthreads();
    int incl = x + ((wid > 0) ? wsum[wid - 1] : 0);
    int btotal = wsum[7];

    if (tid == 0) {
        if (b == 0) {
            atomicExch(&g_state[0], (2ull << 32) | (unsigned)btotal);
            bprefix = 0;
        } else {
            atomicExch(&g_state[b], (1ull << 32) | (unsigned)btotal);
            long long ex = 0;
            int pred = b - 1;
            while (true) {
                unsigned long long s =
                    *((volatile unsigned long long*)&g_state[pred]);
                unsigned st = (unsigned)(s >> 32);
                if (st == 0) continue;
                ex += (unsigned)s;
                if (st == 2) break;
                pred--;
            }
            atomicExch(&g_state[b], (2ull << 32) | (unsigned)(ex + btotal));
            bprefix = (int)ex;
        }
    }
    __syncthreads();

    if (i < NN) {
        int o = bprefix + incl - v;
        g_offs[i] = o;
        g_cursor[i] = o;
    }
    if (i == 0) g_offs[NN] = NE;
}

// ---------------- K3: scatter into CSR (4 atomics batched -> 4 stores) -------
__global__ __launch_bounds__(256) void k_scatter(const int* __restrict__ src,
                                                 const int* __restrict__ dst) {
    int t = blockIdx.x * blockDim.x + threadIdx.x;
    if (t >= NE / 4) return;
    int4 s4 = ((const int4*)src)[t];
    int4 d4 = ((const int4*)dst)[t];
    int p0 = atomicAdd(&g_cursor[clampidx(d4.x)], 1);
    int p1 = atomicAdd(&g_cursor[clampidx(d4.y)], 1);
    int p2 = atomicAdd(&g_cursor[clampidx(d4.z)], 1);
    int p3 = atomicAdd(&g_cursor[clampidx(d4.w)], 1);
    g_csr_src[p0] = clampidx(s4.x);
    g_csr_src[p1] = clampidx(s4.y);
    g_csr_src[p2] = clampidx(s4.z);
    g_csr_src[p3] = clampidx(s4.w);
}

// ---------------- K4: ft = feat @ W  (128x64 tile, 8 rows x 4 cols/thread) ---
__global__ __launch_bounds__(256, 3) void k_gemm(const float* __restrict__ feat,
                                                 const float* __restrict__ Wm) {
    __shared__ float wsm[INF_ * OUTF];   // 32 KB
    int tid = threadIdx.x;

    for (int i = tid; i < (INF_ * OUTF) / 4; i += 256)
        ((float4*)wsm)[i] = ((const float4*)Wm)[i];
    __syncthreads();

    int rg = tid >> 4;                         // 0..15 row group (8 rows each)
    int c0 = (tid & 15) * 4;                   // 4 cols
    int row0 = blockIdx.x * 128 + rg * 8;

    int r[8];
#pragma unroll
    for (int i = 0; i < 8; i++) r[i] = (row0 + i < NN) ? row0 + i : 0;

    unsigned long long acc[8][2];
#pragma unroll
    for (int i = 0; i < 8; i++) { acc[i][0] = 0ull; acc[i][1] = 0ull; }

    for (int kk = 0; kk < INF_ / 4; kk++) {
        float4 fr[8];
#pragma unroll
        for (int i = 0; i < 8; i++)
            fr[i] = ((const float4*)(feat + (size_t)r[i] * INF_))[kk];
#pragma unroll
        for (int j = 0; j < 4; j++) {
            float4 w4 = *(const float4*)(wsm + (kk * 4 + j) * OUTF + c0);
            unsigned long long bxy = pack2(w4.x, w4.y);
            unsigned long long bzw = pack2(w4.z, w4.w);
#pragma unroll
            for (int i = 0; i < 8; i++) {
                float f = (j == 0) ? fr[i].x : (j == 1) ? fr[i].y
                         : (j == 2) ? fr[i].z : fr[i].w;
                unsigned long long a2 = pack2(f, f);
                fma2(acc[i][0], a2, bxy);
                fma2(acc[i][1], a2, bzw);
            }
        }
    }

#pragma unroll
    for (int i = 0; i < 8; i++) {
        int row = row0 + i;
        if (row < NN) {
            float4 o;
            unpack2(acc[i][0], o.x, o.y);
            unpack2(acc[i][1], o.z, o.w);
            *(float4*)(g_ft + (size_t)row * OUTF + c0) = o;
        }
    }
}

// ---------------- K5: fused score + ONLINE softmax + aggregation -------------
// One warp per node; lane l owns output dims [2l, 2l+1]. 4-edge fold groups
// (identical arithmetic to the R12 best) with ONE-DEEP SOFTWARE PIPELINE:
// next group's index+feature loads are issued before the current group's
// SHFL/exp processing, overlapping the ~500-cyc gather chain with compute.
__global__ __launch_bounds__(256) void k_aggregate(float* __restrict__ out) {
    int w = threadIdx.x >> 5;
    int lane = threadIdx.x & 31;
    int node = blockIdx.x * 8 + w;
    if (node >= NN) return;

    int lo = g_offs[node];
    int hi = g_offs[node + 1];
    if (lane == 0) g_deg[node] = 0;          // reset for next replay

    float2 df = *(const float2*)(g_ft + (size_t)node * OUTF + lane * 2);

    float m = -CUDART_INF_F;
    float s = 0.f;
    float2 acc = make_float2(0.f, 0.f);
    bool hi16 = (lane & 16) != 0;

    int i = lo;
    if (i + 3 < hi) {
        // prologue: load group 0
        int ci0 = g_csr_src[i],     ci1 = g_csr_src[i + 1];
        int ci2 = g_csr_src[i + 2], ci3 = g_csr_src[i + 3];
        float2 cf0 = *(const float2*)(g_ft + (size_t)ci0 * OUTF + lane * 2);
        float2 cf1 = *(const float2*)(g_ft + (size_t)ci1 * OUTF + lane * 2);
        float2 cf2 = *(const float2*)(g_ft + (size_t)ci2 * OUTF + lane * 2);
        float2 cf3 = *(const float2*)(g_ft + (size_t)ci3 * OUTF + lane * 2);

        while (true) {
            int inext = i + 4;
            bool more = (inext + 3 < hi);

            // PREFETCH next group (independent of current processing)
            float2 nf0, nf1, nf2, nf3;
            if (more) {
                int ni0 = g_csr_src[inext],     ni1 = g_csr_src[inext + 1];
                int ni2 = g_csr_src[inext + 2], ni3 = g_csr_src[inext + 3];
                nf0 = *(const float2*)(g_ft + (size_t)ni0 * OUTF + lane * 2);
                nf1 = *(const float2*)(g_ft + (size_t)ni1 * OUTF + lane * 2);
                nf2 = *(const float2*)(g_ft + (size_t)ni2 * OUTF + lane * 2);
                nf3 = *(const float2*)(g_ft + (size_t)ni3 * OUTF + lane * 2);
            }

            // PROCESS current group (same arithmetic as R12)
            float p0 = cf0.x * df.x + cf0.y * df.y;
            float p1 = cf1.x * df.x + cf1.y * df.y;
            float p2 = cf2.x * df.x + cf2.y * df.y;
            float p3 = cf3.x * df.x + cf3.y * df.y;
            float a0, a1, a2, a3;
            fold_pair(p0, p1, hi16, a0, a1);
            fold_pair(p2, p3, hi16, a2, a3);
            float mn = fmaxf(fmaxf(a0, a1), fmaxf(a2, a3));
            if (mn > m) {                      // warp-uniform branch
                float rsc = __expf(m - mn);    // first hit: exp(-inf)=0
                s *= rsc; acc.x *= rsc; acc.y *= rsc;
                m = mn;
            }
            float w0 = __expf(a0 - m);
            float w1 = __expf(a1 - m);
            float w2 = __expf(a2 - m);
            float w3 = __expf(a3 - m);
            s += (w0 + w1) + (w2 + w3);
            acc.x += w0 * cf0.x + w1 * cf1.x + w2 * cf2.x + w3 * cf3.x;
            acc.y += w0 * cf0.y + w1 * cf1.y + w2 * cf2.y + w3 * cf3.y;

            i = inext;
            if (!more) break;
            cf0 = nf0; cf1 = nf1; cf2 = nf2; cf3 = nf3;
        }
    }
    // remainder (0-3 edges): plain butterfly
    for (; i < hi; i++) {
        int s0 = g_csr_src[i];
        float2 f0 = *(const float2*)(g_ft + (size_t)s0 * OUTF + lane * 2);
        float p0 = f0.x * df.x + f0.y * df.y;
#pragma unroll
        for (int o = 16; o; o >>= 1) p0 += __shfl_xor_sync(0xffffffffu, p0, o);
        if (p0 > m) {
            float rsc = __expf(m - p0);
            s *= rsc; acc.x *= rsc; acc.y *= rsc;
            m = p0;
        }
        float w0 = __expf(p0 - m);
        s += w0;
        acc.x += w0 * f0.x;
        acc.y += w0 * f0.y;
    }

    if (hi > lo) {
        float inv = 1.f / s;
        acc.x *= inv;
        acc.y *= inv;
    }
    *(float2*)(out + (size_t)node * OUTF + lane * 2) = acc;
}

// ---------------- launch ------------------------------------------------------
// Two independent chains overlapped via capture-legal stream fork:
//   main:  deg -> scan -> scatter ──┐
//   side:  gemm ────────────────────┴─> aggregate (main)
extern "C" void kernel_launch(void* const* d_in, const int* in_sizes, int n_in,
                              void* d_out, int out_size) {
    const float* feat = (const float*)d_in[0];
    const float* Wm   = (const float*)d_in[1];
    const int*   src  = (const int*)d_in[2];
    const int*   dst  = (const int*)d_in[3];
    float* out = (float*)d_out;

    int nbE4 = (NE / 4 + 255) / 256;         // 1563
    int nbG  = (NN + 127) / 128;             // 782
    int nbA  = (NN + 7) / 8;                 // 12500

    static cudaStream_t s2 = nullptr;
    static cudaEvent_t evFork = nullptr, evJoin = nullptr;
    static bool initTried = false;
    if (!initTried) {
        initTried = true;
        if (cudaStreamCreateWithFlags(&s2, cudaStreamNonBlocking) != cudaSuccess)
            s2 = nullptr;
        if (s2) {
            cudaEventCreateWithFlags(&evFork, cudaEventDisableTiming);
            cudaEventCreateWithFlags(&evJoin, cudaEventDisableTiming);
        }
    }

    if (s2) {
        cudaEventRecord(evFork, 0);
        cudaStreamWaitEvent(s2, evFork, 0);
        k_gemm<<<nbG, 256, 0, s2>>>(feat, Wm);

        k_deg<<<nbE4, 256>>>(dst);
        k_scan<<<SCAN_NB, 256>>>();
        k_scatter<<<nbE4, 256>>>(src, dst);

        cudaEventRecord(evJoin, s2);
        cudaStreamWaitEvent(0, evJoin, 0);
        k_aggregate<<<nbA, 256>>>(out);
    } else {
        k_deg<<<nbE4, 256>>>(dst);
        k_scan<<<SCAN_NB, 256>>>();
        k_scatter<<<nbE4, 256>>>(src, dst);
        k_gemm<<<nbG, 256>>>(feat, Wm);
        k_aggregate<<<nbA, 256>>>(out);
    }
}

// round 17
// speedup vs baseline: 1.0160x; 1.0160x over previous
#include <cuda_runtime.h>
#include <cuda_bf16.h>
#include <math_constants.h>

// Problem shape (fixed by dataset)
#define NN 100000
#define NE 1600000
#define INF_ 128
#define OUTF 64
#define SCAN_NB 391          // ceil(NN/256)

// ---------------- device scratch (static: no runtime allocation) -------------
// NOTE lifecycle: g_deg is zero at every kernel_launch entry — zero-initialized
// at load, and re-zeroed by k_aggregate at the end of every executed call
// (graph capture does not execute, so the invariant holds across replays).
__device__ float g_ft[(size_t)NN * OUTF];       // projected features  [N,64]
__device__ int   g_deg[NN];                     // in-degree histogram
__device__ int   g_offs[NN + 1];                // CSR offsets by dst
__device__ int   g_cursor[NN];                  // scatter cursors
__device__ int   g_csr_src[NE];                 // src node per CSR slot
__device__ unsigned long long g_state[SCAN_NB]; // lookback: (status<<32)|sum

__device__ __forceinline__ int clampidx(int v) {
    unsigned u = (unsigned)v;
    return (u < (unsigned)NN) ? v : 0;
}

// packed f32x2 helpers (Blackwell: FFMA2 only reachable from PTX)
__device__ __forceinline__ unsigned long long pack2(float lo, float hi) {
    unsigned long long r;
    asm("mov.b64 %0, {%1, %2};" : "=l"(r) : "f"(lo), "f"(hi));
    return r;
}
__device__ __forceinline__ void unpack2(unsigned long long v, float& lo, float& hi) {
    asm("mov.b64 {%0, %1}, %2;" : "=f"(lo), "=f"(hi) : "l"(v));
}
__device__ __forceinline__ void fma2(unsigned long long& d,
                                     unsigned long long a, unsigned long long b) {
    asm("fma.rn.f32x2 %0, %1, %2, %0;" : "+l"(d) : "l"(a), "l"(b));
}

// half-warp fold reduce of an (even, odd) edge pair -> both lanes get both sums
__device__ __forceinline__ void fold_pair(float pe, float po, bool hi16,
                                          float& ae, float& ao) {
    float u = hi16 ? po : pe;
    u += __shfl_xor_sync(0xffffffffu, hi16 ? pe : po, 16);
#pragma unroll
    for (int o = 8; o; o >>= 1) u += __shfl_xor_sync(0xffffffffu, u, o);
    float ot = __shfl_xor_sync(0xffffffffu, u, 16);
    ae = hi16 ? ot : u;
    ao = hi16 ? u : ot;
}

// ---------------- K1: in-degree histogram (8 edges/thread) -------------------
__global__ __launch_bounds__(256) void k_deg(const int* __restrict__ dst) {
    int t = blockIdx.x * blockDim.x + threadIdx.x;
    if (t < SCAN_NB) g_state[t] = 0ull;       // consumed by k_scan (next launch)
    if (t >= NE / 8) return;
    const int4* dp = (const int4*)dst;
    int4 a = dp[t * 2];
    int4 b = dp[t * 2 + 1];
    atomicAdd(&g_deg[clampidx(a.x)], 1);
    atomicAdd(&g_deg[clampidx(a.y)], 1);
    atomicAdd(&g_deg[clampidx(a.z)], 1);
    atomicAdd(&g_deg[clampidx(a.w)], 1);
    atomicAdd(&g_deg[clampidx(b.x)], 1);
    atomicAdd(&g_deg[clampidx(b.y)], 1);
    atomicAdd(&g_deg[clampidx(b.z)], 1);
    atomicAdd(&g_deg[clampidx(b.w)], 1);
}

// ---------------- K2: single-pass decoupled-lookback exclusive scan ----------
__global__ __launch_bounds__(256) void k_scan() {
    __shared__ int wsum[8];
    __shared__ int bprefix;
    int b = blockIdx.x;
    int tid = threadIdx.x;
    int lane = tid & 31;
    int wid = tid >> 5;
    int i = b * 256 + tid;

    int v = (i < NN) ? g_deg[i] : 0;
    int x = v;
#pragma unroll
    for (int o = 1; o < 32; o <<= 1) {
        int t = __shfl_up_sync(0xffffffffu, x, o);
        if (lane >= o) x += t;
    }
    if (lane == 31) wsum[wid] = x;
    __syncthreads();
    if (wid == 0) {
        int y = (lane < 8) ? wsum[lane] : 0;
#pragma unroll
        for (int o = 1; o < 8; o <<= 1) {
            int t = __shfl_up_sync(0xffffffffu, y, o);
            if (lane >= o) y += t;
        }
        if (lane < 8) wsum[lane] = y;
    }
    __syncthreads();
    int incl = x + ((wid > 0) ? wsum[wid - 1] : 0);
    int btotal = wsum[7];

    if (tid == 0) {
        if (b == 0) {
            atomicExch(&g_state[0], (2ull << 32) | (unsigned)btotal);
            bprefix = 0;
        } else {
            atomicExch(&g_state[b], (1ull << 32) | (unsigned)btotal);
            long long ex = 0;
            int pred = b - 1;
            while (true) {
                unsigned long long s =
                    *((volatile unsigned long long*)&g_state[pred]);
                unsigned st = (unsigned)(s >> 32);
                if (st == 0) continue;
                ex += (unsigned)s;
                if (st == 2) break;
                pred--;
            }
            atomicExch(&g_state[b], (2ull << 32) | (unsigned)(ex + btotal));
            bprefix = (int)ex;
        }
    }
    __syncthreads();

    if (i < NN) {
        int o = bprefix + incl - v;
        g_offs[i] = o;
        g_cursor[i] = o;
    }
    if (i == 0) g_offs[NN] = NE;
}

// ---------------- K3: scatter into CSR (8 atomics batched -> 8 stores) -------
__global__ __launch_bounds__(256) void k_scatter(const int* __restrict__ src,
                                                 const int* __restrict__ dst) {
    int t = blockIdx.x * blockDim.x + threadIdx.x;
    if (t >= NE / 8) return;
    const int4* sp = (const int4*)src;
    const int4* dp = (const int4*)dst;
    int4 sa = sp[t * 2], sb = sp[t * 2 + 1];
    int4 da = dp[t * 2], db = dp[t * 2 + 1];
    // issue all 8 atomics first (8 independent ATOMGs in flight), then stores
    int p0 = atomicAdd(&g_cursor[clampidx(da.x)], 1);
    int p1 = atomicAdd(&g_cursor[clampidx(da.y)], 1);
    int p2 = atomicAdd(&g_cursor[clampidx(da.z)], 1);
    int p3 = atomicAdd(&g_cursor[clampidx(da.w)], 1);
    int p4 = atomicAdd(&g_cursor[clampidx(db.x)], 1);
    int p5 = atomicAdd(&g_cursor[clampidx(db.y)], 1);
    int p6 = atomicAdd(&g_cursor[clampidx(db.z)], 1);
    int p7 = atomicAdd(&g_cursor[clampidx(db.w)], 1);
    g_csr_src[p0] = clampidx(sa.x);
    g_csr_src[p1] = clampidx(sa.y);
    g_csr_src[p2] = clampidx(sa.z);
    g_csr_src[p3] = clampidx(sa.w);
    g_csr_src[p4] = clampidx(sb.x);
    g_csr_src[p5] = clampidx(sb.y);
    g_csr_src[p6] = clampidx(sb.z);
    g_csr_src[p7] = clampidx(sb.w);
}

// ---------------- K4: ft = feat @ W  (128x64 tile, 8 rows x 4 cols/thread) ---
__global__ __launch_bounds__(256, 3) void k_gemm(const float* __restrict__ feat,
                                                 const float* __restrict__ Wm) {
    __shared__ float wsm[INF_ * OUTF];   // 32 KB
    int tid = threadIdx.x;

    for (int i = tid; i < (INF_ * OUTF) / 4; i += 256)
        ((float4*)wsm)[i] = ((const float4*)Wm)[i];
    __syncthreads();

    int rg = tid >> 4;                         // 0..15 row group (8 rows each)
    int c0 = (tid & 15) * 4;                   // 4 cols
    int row0 = blockIdx.x * 128 + rg * 8;

    int r[8];
#pragma unroll
    for (int i = 0; i < 8; i++) r[i] = (row0 + i < NN) ? row0 + i : 0;

    unsigned long long acc[8][2];
#pragma unroll
    for (int i = 0; i < 8; i++) { acc[i][0] = 0ull; acc[i][1] = 0ull; }

    for (int kk = 0; kk < INF_ / 4; kk++) {
        float4 fr[8];
#pragma unroll
        for (int i = 0; i < 8; i++)
            fr[i] = ((const float4*)(feat + (size_t)r[i] * INF_))[kk];
#pragma unroll
        for (int j = 0; j < 4; j++) {
            float4 w4 = *(const float4*)(wsm + (kk * 4 + j) * OUTF + c0);
            unsigned long long bxy = pack2(w4.x, w4.y);
            unsigned long long bzw = pack2(w4.z, w4.w);
#pragma unroll
            for (int i = 0; i < 8; i++) {
                float f = (j == 0) ? fr[i].x : (j == 1) ? fr[i].y
                         : (j == 2) ? fr[i].z : fr[i].w;
                unsigned long long a2 = pack2(f, f);
                fma2(acc[i][0], a2, bxy);
                fma2(acc[i][1], a2, bzw);
            }
        }
    }

#pragma unroll
    for (int i = 0; i < 8; i++) {
        int row = row0 + i;
        if (row < NN) {
            float4 o;
            unpack2(acc[i][0], o.x, o.y);
            unpack2(acc[i][1], o.z, o.w);
            *(float4*)(g_ft + (size_t)row * OUTF + c0) = o;
        }
    }
}

// ---------------- K5: fused score + ONLINE softmax + aggregation -------------
// One warp per node; lane l owns output dims [2l, 2l+1].
// EXACT R12 structure (4-edge fold groups) — three rewrites lost to it.
__global__ __launch_bounds__(256, 4) void k_aggregate(float* __restrict__ out) {
    int w = threadIdx.x >> 5;
    int lane = threadIdx.x & 31;
    int node = blockIdx.x * 8 + w;
    if (node >= NN) return;

    int lo = g_offs[node];
    int hi = g_offs[node + 1];
    if (lane == 0) g_deg[node] = 0;          // reset for next replay

    float2 df = *(const float2*)(g_ft + (size_t)node * OUTF + lane * 2);

    float m = -CUDART_INF_F;
    float s = 0.f;
    float2 acc = make_float2(0.f, 0.f);
    bool hi16 = (lane & 16) != 0;

    int i = lo;
    for (; i + 3 < hi; i += 4) {
        int s0 = g_csr_src[i];
        int s1 = g_csr_src[i + 1];
        int s2 = g_csr_src[i + 2];
        int s3 = g_csr_src[i + 3];
        float2 f0 = *(const float2*)(g_ft + (size_t)s0 * OUTF + lane * 2);
        float2 f1 = *(const float2*)(g_ft + (size_t)s1 * OUTF + lane * 2);
        float2 f2 = *(const float2*)(g_ft + (size_t)s2 * OUTF + lane * 2);
        float2 f3 = *(const float2*)(g_ft + (size_t)s3 * OUTF + lane * 2);
        float p0 = f0.x * df.x + f0.y * df.y;
        float p1 = f1.x * df.x + f1.y * df.y;
        float p2 = f2.x * df.x + f2.y * df.y;
        float p3 = f3.x * df.x + f3.y * df.y;

        float a0, a1, a2, a3;
        fold_pair(p0, p1, hi16, a0, a1);
        fold_pair(p2, p3, hi16, a2, a3);

        float mn = fmaxf(fmaxf(a0, a1), fmaxf(a2, a3));
        if (mn > m) {                          // warp-uniform branch
            float rsc = __expf(m - mn);        // first hit: exp(-inf)=0
            s *= rsc; acc.x *= rsc; acc.y *= rsc;
            m = mn;
        }
        float w0 = __expf(a0 - m);
        float w1 = __expf(a1 - m);
        float w2 = __expf(a2 - m);
        float w3 = __expf(a3 - m);
        s += (w0 + w1) + (w2 + w3);
        acc.x += w0 * f0.x + w1 * f1.x + w2 * f2.x + w3 * f3.x;
        acc.y += w0 * f0.y + w1 * f1.y + w2 * f2.y + w3 * f3.y;
    }
    // remainder (0-3 edges): plain butterfly
    for (; i < hi; i++) {
        int s0 = g_csr_src[i];
        float2 f0 = *(const float2*)(g_ft + (size_t)s0 * OUTF + lane * 2);
        float p0 = f0.x * df.x + f0.y * df.y;
#pragma unroll
        for (int o = 16; o; o >>= 1) p0 += __shfl_xor_sync(0xffffffffu, p0, o);
        if (p0 > m) {
            float rsc = __expf(m - p0);
            s *= rsc; acc.x *= rsc; acc.y *= rsc;
            m = p0;
        }
        float w0 = __expf(p0 - m);
        s += w0;
        acc.x += w0 * f0.x;
        acc.y += w0 * f0.y;
    }

    if (hi > lo) {
        float inv = 1.f / s;
        acc.x *= inv;
        acc.y *= inv;
    }
    *(float2*)(out + (size_t)node * OUTF + lane * 2) = acc;
}

// ---------------- launch ------------------------------------------------------
// Two independent chains overlapped via capture-legal stream fork:
//   main:  deg -> scan -> scatter ──┐
//   side:  gemm ────────────────────┴─> aggregate (main)
extern "C" void kernel_launch(void* const* d_in, const int* in_sizes, int n_in,
                              void* d_out, int out_size) {
    const float* feat = (const float*)d_in[0];
    const float* Wm   = (const float*)d_in[1];
    const int*   src  = (const int*)d_in[2];
    const int*   dst  = (const int*)d_in[3];
    float* out = (float*)d_out;

    int nbE8 = (NE / 8 + 255) / 256;         // 782
    int nbG  = (NN + 127) / 128;             // 782
    int nbA  = (NN + 7) / 8;                 // 12500

    static cudaStream_t s2 = nullptr;
    static cudaEvent_t evFork = nullptr, evJoin = nullptr;
    static bool initTried = false;
    if (!initTried) {
        initTried = true;
        if (cudaStreamCreateWithFlags(&s2, cudaStreamNonBlocking) != cudaSuccess)
            s2 = nullptr;
        if (s2) {
            cudaEventCreateWithFlags(&evFork, cudaEventDisableTiming);
            cudaEventCreateWithFlags(&evJoin, cudaEventDisableTiming);
        }
    }

    if (s2) {
        cudaEventRecord(evFork, 0);
        cudaStreamWaitEvent(s2, evFork, 0);
        k_gemm<<<nbG, 256, 0, s2>>>(feat, Wm);

        k_deg<<<nbE8, 256>>>(dst);
        k_scan<<<SCAN_NB, 256>>>();
        k_scatter<<<nbE8, 256>>>(src, dst);

        cudaEventRecord(evJoin, s2);
        cudaStreamWaitEvent(0, evJoin, 0);
        k_aggregate<<<nbA, 256>>>(out);
    } else {
        k_deg<<<nbE8, 256>>>(dst);
        k_scan<<<SCAN_NB, 256>>>();
        k_scatter<<<nbE8, 256>>>(src, dst);
        k_gemm<<<nbG, 256>>>(feat, Wm);
        k_aggregate<<<nbA, 256>>>(out);
    }
}